// round 6
// baseline (speedup 1.0000x reference)
#include <cuda_runtime.h>
#include <math.h>

#define Bn 16
#define Cn 256
#define Hn 128
#define Wn 128
#define HWn (Hn*Wn)
#define PO 20
#define NP (PO*PO)
#define MIDn 16
#define OCn 32
#define OHn 64
#define OWn 64
#define OHWn (OHn*OWn)
#define NBLK_CONV 512

// ---- scratch (static device globals: no allocs allowed) ----
__device__ float g_xp[Bn*Cn*NP];            // pooled 20x20 per (b,c)   [c][n]
__device__ float g_xpT[Bn*NP*Cn];           // transposed pooled        [n][c]
__device__ float g_x2[(size_t)Bn*MIDn*HWn]; // grouped channel means
__device__ float g_attn[Bn*Cn];
__device__ int   g_maxid[MIDn];
__device__ float g_scale[MIDn];
__device__ float g_xc[(size_t)Bn*OCn*HWn];  // concat(x1,x2)
__device__ float g_smean[Bn*HWn];
__device__ float g_smax[Bn*HWn];
__device__ float g_siga[Bn*HWn];            // sigmoid(LSA conv)
__device__ float g_y[(size_t)Bn*OCn*OHWn];  // pre-BN conv output
__device__ float g_part[NBLK_CONV*OCn*2];   // per-block BN partials (fixed slots)
__device__ float g_bnA[OCn];
__device__ float g_bnB[OCn];

__device__ __forceinline__ float fsig(float x) { return 1.0f / (1.0f + __expf(-x)); }

// ---- packed f32x2 helpers ----
__device__ __forceinline__ unsigned long long pk2(float lo, float hi) {
    unsigned long long r;
    asm("mov.b64 %0, {%1, %2};" : "=l"(r) : "f"(lo), "f"(hi));
    return r;
}
__device__ __forceinline__ float2 upk2(unsigned long long u) {
    float2 f;
    asm("mov.b64 {%0, %1}, %2;" : "=f"(f.x), "=f"(f.y) : "l"(u));
    return f;
}
__device__ __forceinline__ void ffma2(unsigned long long& a, unsigned long long v, unsigned long long w) {
    asm("fma.rn.f32x2 %0, %1, %2, %0;" : "+l"(a) : "l"(v), "l"(w));
}
__device__ __forceinline__ unsigned long long fmul2(unsigned long long a, unsigned long long b) {
    unsigned long long r;
    asm("mul.rn.f32x2 %0, %1, %2;" : "=l"(r) : "l"(a), "l"(b));
    return r;
}
__device__ __forceinline__ unsigned long long fadd2(unsigned long long a, unsigned long long b) {
    unsigned long long r;
    asm("add.rn.f32x2 %0, %1, %2;" : "=l"(r) : "l"(a), "l"(b));
    return r;
}

// ---- K1: slab-fused adaptive-pool + grouped channel mean ----
// Block = (b, group m, 32-row slab s). Row-bin boundaries align with 32-row
// slabs (floor(5*128/20)=32), so each slab holds bins 5s..5s+4 completely.
__global__ void __launch_bounds__(256) k_pool_gm(const float* __restrict__ x) {
    int blk = blockIdx.x;          // b*64 + m*4 + s
    int b = blk >> 6, m = (blk >> 2) & 15, s = blk & 3;
    int t = threadIdx.x;

    __shared__ float4 sm4[32 * 33];        // 32 rows x 32 quads, pad 1 quad/row
    __shared__ float poolbuf[16][112];     // [c][n-local], padded

    float4 acc[4];
    #pragma unroll
    for (int k = 0; k < 4; k++) acc[k] = make_float4(0.f, 0.f, 0.f, 0.f);

    const float4* base = (const float4*)x
        + ((size_t)(b * Cn + m * 16)) * 4096 + s * 1024;
    const float* smf = (const float*)sm4;

    for (int c = 0; c < 16; c++) {
        const float4* pl = base + (size_t)c * 4096;
        #pragma unroll
        for (int k = 0; k < 4; k++) {
            int f = k * 256 + t;           // 0..1023 quad in slab
            float4 v = pl[f];
            acc[k].x += v.x; acc[k].y += v.y; acc[k].z += v.z; acc[k].w += v.w;
            sm4[(f >> 5) * 33 + (f & 31)] = v;
        }
        __syncthreads();
        if (t < 100) {
            int i = t / 20, j = t % 20;
            int gi = 5 * s + i;
            int si = (gi * Hn) / PO - 32 * s;
            int ei = ((gi + 1) * Hn + PO - 1) / PO - 32 * s;
            int sj = (j * Wn) / PO;
            int ej = ((j + 1) * Wn + PO - 1) / PO;
            float acc2 = 0.f;
            for (int r = si; r < ei; r++) {
                const float* row = smf + r * 132;
                for (int w = sj; w < ej; w++) acc2 += row[w];
            }
            float val = acc2 / (float)((ei - si) * (ej - sj));
            g_xp[((size_t)(b * Cn + m * 16 + c)) * NP + gi * 20 + j] = val;
            poolbuf[c][t] = val;
        }
        __syncthreads();
    }

    // grouped mean slab
    float4* x2 = (float4*)g_x2 + ((size_t)(b * MIDn + m)) * 4096 + s * 1024;
    #pragma unroll
    for (int k = 0; k < 4; k++) {
        float4 v = acc[k];
        v.x *= (1.f/16.f); v.y *= (1.f/16.f); v.z *= (1.f/16.f); v.w *= (1.f/16.f);
        x2[k * 256 + t] = v;
    }

    // transposed pooled writes: row n gets 16 contiguous channels (64B)
    if (t < 100) {
        int n = 100 * s + t;
        float4* dst = (float4*)(g_xpT + ((size_t)b * NP + n) * Cn + m * 16);
        #pragma unroll
        for (int cq = 0; cq < 4; cq++) {
            dst[cq] = make_float4(poolbuf[cq * 4 + 0][t], poolbuf[cq * 4 + 1][t],
                                  poolbuf[cq * 4 + 2][t], poolbuf[cq * 4 + 3][t]);
        }
    }
}

// ---- K2: fused colmean + feat + attn, one block per batch (512 threads) ----
__global__ void __launch_bounds__(512) k_soca(const float* __restrict__ lw,
                                              const float* __restrict__ lb) {
    int b = blockIdx.x;
    int t = threadIdx.x;
    int lane = t & 31, w = t >> 5;       // 16 warps
    __shared__ float cm[NP];
    __shared__ float sf[Cn];
    __shared__ float red[16];

    // stage 1: column means via transposed layout (contiguous per thread)
    float s = 0.f;
    if (t < NP) {
        const float4* row = (const float4*)(g_xpT + ((size_t)b * NP + t) * Cn);
        float4 a0 = make_float4(0.f, 0.f, 0.f, 0.f);
        #pragma unroll 8
        for (int i = 0; i < 64; i++) {
            float4 v = row[i];
            a0.x += v.x; a0.y += v.y; a0.z += v.z; a0.w += v.w;
        }
        s = (a0.x + a0.y + a0.z + a0.w) * (1.0f / Cn);
    }
    float r = (t < NP) ? s : 0.f;
    #pragma unroll
    for (int d = 16; d; d >>= 1) r += __shfl_xor_sync(0xffffffffu, r, d);
    if (lane == 0) red[w] = r;
    __syncthreads();
    float a = 0.f;
    #pragma unroll
    for (int i = 0; i < 16; i++) a += red[i];
    float mm = a * (1.0f / NP);
    if (t < NP) cm[t] = s - mm;
    __syncthreads();

    // stage 2: feat[c] = dot(xp[b,c,:], cm)/(NP-1)
    for (int cc = 0; cc < 16; cc++) {
        int c = w * 16 + cc;
        const float* xp = g_xp + ((size_t)b * Cn + c) * NP;
        float acc = 0.f;
        for (int n = lane; n < NP; n += 32) acc += xp[n] * cm[n];
        #pragma unroll
        for (int d = 16; d; d >>= 1) acc += __shfl_xor_sync(0xffffffffu, acc, d);
        if (lane == 0) sf[c] = acc * (1.0f / (NP - 1));
    }
    __syncthreads();

    // stage 3: attn = sigmoid(feat @ W^T + b)
    for (int oo = 0; oo < 16; oo++) {
        int o = oo * 16 + w;
        const float* wr = lw + o * Cn;
        float acc = 0.f;
        #pragma unroll
        for (int i = lane; i < Cn; i += 32) acc += sf[i] * wr[i];
        #pragma unroll
        for (int d = 16; d; d >>= 1) acc += __shfl_xor_sync(0xffffffffu, acc, d);
        if (lane == 0) g_attn[b * Cn + o] = fsig(acc + lb[o]);
    }
}

// ---- K3: score = mean_b(attn), stable descending top-16, sorted ids ----
__global__ void k_topk() {
    int o = threadIdx.x;   // 256 threads
    __shared__ float sc[Cn];
    __shared__ int fl[Cn];
    float s = 0.f;
    for (int b = 0; b < Bn; b++) s += g_attn[b * Cn + o];
    s *= (1.0f / Bn);
    sc[o] = s;
    __syncthreads();
    float so = sc[o];
    int r = 0;
    for (int j = 0; j < Cn; j++) {
        float sj = sc[j];
        r += (sj > so) || (sj == so && j < o);   // stable argsort(-score)
    }
    fl[o] = (r < MIDn) ? 1 : 0;
    __syncthreads();
    if (r < MIDn) {
        int pos = 0;
        for (int j = 0; j < o; j++) pos += fl[j];
        g_maxid[pos] = o;             // ascending ids == jnp.sort(score_id[:16])
        g_scale[pos] = 1.0f + so;
    }
}

// ---- K4: build xc; two threads per pixel-quad (x1-half / x2-half) ----
__global__ void __launch_bounds__(256) k_build(const float* __restrict__ x) {
    __shared__ int sid[MIDn];
    __shared__ float ssc[MIDn];
    __shared__ float4 s_sum[128];
    __shared__ float4 s_max[128];
    if (threadIdx.x < MIDn) {
        sid[threadIdx.x] = g_maxid[threadIdx.x];
        ssc[threadIdx.x] = g_scale[threadIdx.x];
    }
    __syncthreads();
    int half = threadIdx.x >> 7, lt = threadIdx.x & 127;
    int qg = blockIdx.x * 128 + lt;     // grid = 512 blocks
    int b = qg >> 12;
    int q = qg & 4095;
    float4* xcb = (float4*)g_xc + (size_t)b * OCn * 4096 + q;

    float4 csum = make_float4(0.f, 0.f, 0.f, 0.f);
    float4 cmax = make_float4(-3.4e38f, -3.4e38f, -3.4e38f, -3.4e38f);
    if (half == 0) {
        const float4* xb = (const float4*)x + (size_t)b * Cn * 4096 + q;
        #pragma unroll
        for (int k = 0; k < MIDn; k++) {
            float4 v = xb[(size_t)sid[k] * 4096];
            float sk = ssc[k];
            v.x *= sk; v.y *= sk; v.z *= sk; v.w *= sk;
            xcb[(size_t)k * 4096] = v;
            csum.x += v.x; csum.y += v.y; csum.z += v.z; csum.w += v.w;
            cmax.x = fmaxf(cmax.x, v.x); cmax.y = fmaxf(cmax.y, v.y);
            cmax.z = fmaxf(cmax.z, v.z); cmax.w = fmaxf(cmax.w, v.w);
        }
    } else {
        const float4* x2 = (const float4*)g_x2 + (size_t)b * MIDn * 4096 + q;
        #pragma unroll
        for (int m = 0; m < MIDn; m++) {
            float4 v = x2[(size_t)m * 4096];
            xcb[(size_t)(MIDn + m) * 4096] = v;
            csum.x += v.x; csum.y += v.y; csum.z += v.z; csum.w += v.w;
            cmax.x = fmaxf(cmax.x, v.x); cmax.y = fmaxf(cmax.y, v.y);
            cmax.z = fmaxf(cmax.z, v.z); cmax.w = fmaxf(cmax.w, v.w);
        }
        s_sum[lt] = csum;
        s_max[lt] = cmax;
    }
    __syncthreads();
    if (half == 0) {
        float4 o = s_sum[lt], x4 = s_max[lt];
        csum.x += o.x; csum.y += o.y; csum.z += o.z; csum.w += o.w;
        cmax.x = fmaxf(cmax.x, x4.x); cmax.y = fmaxf(cmax.y, x4.y);
        cmax.z = fmaxf(cmax.z, x4.z); cmax.w = fmaxf(cmax.w, x4.w);
        csum.x *= (1.f/OCn); csum.y *= (1.f/OCn); csum.z *= (1.f/OCn); csum.w *= (1.f/OCn);
        ((float4*)g_smean)[b * 4096 + q] = csum;
        ((float4*)g_smax)[b * 4096 + q] = cmax;
    }
}

// ---- K5: LSA 7x7 conv (2ch -> 1), sigmoid. One block per (b,row) ----
__global__ void k_lsa(const float* __restrict__ lsa) {
    __shared__ float wv[98];
    if (threadIdx.x < 98) wv[threadIdx.x] = lsa[threadIdx.x];
    __syncthreads();
    int b = blockIdx.x >> 7;
    int yr = blockIdx.x & 127;
    int xc = threadIdx.x;   // 128
    const float* pm = g_smean + b * HWn;
    const float* px = g_smax + b * HWn;
    float acc = 0.f;
    #pragma unroll
    for (int dy = 0; dy < 7; dy++) {
        int ry = yr + dy - 3;
        if (ry < 0 || ry >= Hn) continue;
        #pragma unroll
        for (int dx = 0; dx < 7; dx++) {
            int rx = xc + dx - 3;
            if (rx < 0 || rx >= Wn) continue;
            int off = ry * Wn + rx;
            acc += pm[off] * wv[dy * 7 + dx] + px[off] * wv[49 + dy * 7 + dx];
        }
    }
    g_siga[b * HWn + yr * Wn + xc] = fsig(acc);
}

// ---- K6: 3x3/s2 conv with packed f32x2 over output-channel pairs ----
__global__ void __launch_bounds__(128) k_conv(const float* __restrict__ cw,
                                              const float* __restrict__ cb) {
    __shared__ float2 ws2[OCn * 16 * 9];   // [ic][opair][k]
    __shared__ float sb[OCn];
    __shared__ float bred[4][OCn * 2];
    for (int i = threadIdx.x; i < OCn * 16 * 9; i += 128) {
        int ic = i / 144, rr = i % 144, op = rr / 9, k = rr % 9;
        ws2[i] = make_float2(cw[(2 * op) * (OCn * 9) + ic * 9 + k],
                             cw[(2 * op + 1) * (OCn * 9) + ic * 9 + k]);
    }
    if (threadIdx.x < OCn) sb[threadIdx.x] = cb[threadIdx.x];
    __syncthreads();

    int gid = blockIdx.x * 128 + threadIdx.x;  // 65536 output pixels
    int b = gid >> 12;
    int rem = gid & 4095;
    int oy = rem >> 6, ox = rem & 63;
    int iy0 = 2 * oy - 1, ix0 = 2 * ox - 1;

    const float* sg = g_siga + b * HWn;
    float sv[9];
    int offs[9];
    #pragma unroll
    for (int ky = 0; ky < 3; ky++)
        #pragma unroll
        for (int kx = 0; kx < 3; kx++) {
            int iy = iy0 + ky, ix = ix0 + kx;
            bool ok = (iy >= 0 && iy < Hn && ix >= 0 && ix < Wn);
            int iyc = min(max(iy, 0), Hn - 1), ixc = min(max(ix, 0), Wn - 1);
            offs[ky * 3 + kx] = iyc * Wn + ixc;
            sv[ky * 3 + kx] = ok ? sg[iyc * Wn + ixc] : 0.f;
        }

    unsigned long long acc2[16];
    #pragma unroll
    for (int op = 0; op < 16; op++) acc2[op] = pk2(sb[2 * op], sb[2 * op + 1]);

    const float* xcb = g_xc + (size_t)b * OCn * HWn;
    const unsigned long long* wsu = (const unsigned long long*)ws2;
    #pragma unroll 1
    for (int ic = 0; ic < OCn; ic++) {
        const float* pl = xcb + (size_t)ic * HWn;
        unsigned long long v2[9];
        #pragma unroll
        for (int k = 0; k < 9; k++) {
            float v = pl[offs[k]] * sv[k];
            v2[k] = pk2(v, v);
        }
        const unsigned long long* wb = wsu + ic * 144;
        #pragma unroll
        for (int op = 0; op < 16; op++)
            #pragma unroll
            for (int k = 0; k < 9; k++)
                ffma2(acc2[op], v2[k], wb[op * 9 + k]);
    }

    float* yb = g_y + (size_t)b * OCn * OHWn + rem;
    #pragma unroll
    for (int op = 0; op < 16; op++) {
        float2 f = upk2(acc2[op]);
        yb[(size_t)(2 * op) * OHWn] = f.x;
        yb[(size_t)(2 * op + 1) * OHWn] = f.y;
    }

    int lane = threadIdx.x & 31;
    int w = threadIdx.x >> 5;
    #pragma unroll
    for (int op = 0; op < 16; op++) {
        unsigned long long s2 = acc2[op];
        unsigned long long q2 = fmul2(s2, s2);
        #pragma unroll
        for (int d = 16; d; d >>= 1) {
            s2 = fadd2(s2, __shfl_xor_sync(0xffffffffu, s2, d));
            q2 = fadd2(q2, __shfl_xor_sync(0xffffffffu, q2, d));
        }
        if (lane == 0) {
            float2 fs = upk2(s2), fq = upk2(q2);
            bred[w][4 * op + 0] = fs.x;
            bred[w][4 * op + 1] = fq.x;
            bred[w][4 * op + 2] = fs.y;
            bred[w][4 * op + 3] = fq.y;
        }
    }
    __syncthreads();
    if (threadIdx.x < OCn * 2) {
        float t = bred[0][threadIdx.x] + bred[1][threadIdx.x]
                + bred[2][threadIdx.x] + bred[3][threadIdx.x];
        g_part[blockIdx.x * (OCn * 2) + threadIdx.x] = t;
    }
}

// ---- K7: ordered reduction of BN partials -> scale/shift ----
__global__ void k_bnstat(const float* __restrict__ gamma, const float* __restrict__ beta) {
    int t = threadIdx.x;             // 256: stat = t>>2 (64 stats), sub = t&3
    int stat = t >> 2, sub = t & 3;
    float s = 0.f;
    for (int j = 0; j < NBLK_CONV / 4; j++)
        s += g_part[(size_t)(sub + 4 * j) * (OCn * 2) + stat];
    __shared__ float sr[256];
    __shared__ float tot[OCn * 2];
    sr[t] = s;
    __syncthreads();
    if (t < OCn * 2)
        tot[t] = sr[t * 4] + sr[t * 4 + 1] + sr[t * 4 + 2] + sr[t * 4 + 3];
    __syncthreads();
    if (t < OCn) {
        int op = t >> 1, pr = t & 1;
        float sum = tot[4 * op + 2 * pr];
        float sq  = tot[4 * op + 2 * pr + 1];
        float inv = 1.0f / (float)(Bn * OHWn);
        float mu = sum * inv;
        float var = sq * inv - mu * mu;
        int ch = 2 * op + pr;
        float A = gamma[ch] * rsqrtf(var + 1e-3f);
        g_bnA[ch] = A;
        g_bnB[ch] = beta[ch] - mu * A;
    }
}

// ---- K8: BN-normalize + SiLU -> output, float4 ----
__global__ void __launch_bounds__(256) k_out(float* __restrict__ out) {
    int gid = blockIdx.x * 256 + threadIdx.x;       // float4 index
    int ch = (gid >> 10) & 31;                      // 1024 float4 per (b,o) plane
    float A = g_bnA[ch], Bv = g_bnB[ch];
    float4 y = ((const float4*)g_y)[gid];
    float4 r;
    float yn;
    yn = y.x * A + Bv; r.x = yn * fsig(yn);
    yn = y.y * A + Bv; r.y = yn * fsig(yn);
    yn = y.z * A + Bv; r.z = yn * fsig(yn);
    yn = y.w * A + Bv; r.w = yn * fsig(yn);
    ((float4*)out)[gid] = r;
}

extern "C" void kernel_launch(void* const* d_in, const int* in_sizes, int n_in,
                              void* d_out, int out_size) {
    (void)in_sizes; (void)n_in; (void)out_size;
    const float* x     = (const float*)d_in[0];
    const float* lw    = (const float*)d_in[1];
    const float* lb    = (const float*)d_in[2];
    const float* lsa   = (const float*)d_in[3];
    const float* cw    = (const float*)d_in[4];
    const float* cb    = (const float*)d_in[5];
    const float* gamma = (const float*)d_in[6];
    const float* beta  = (const float*)d_in[7];
    float* out = (float*)d_out;

    k_pool_gm<<<Bn * MIDn * 4, 256>>>(x);
    k_soca  <<<Bn, 512>>>(lw, lb);
    k_topk  <<<1, Cn>>>();
    k_build <<<Bn * HWn / 4 / 128, 256>>>(x);
    k_lsa   <<<Bn * Hn, 128>>>(lsa);
    k_conv  <<<NBLK_CONV, 128>>>(cw, cb);
    k_bnstat<<<1, 256>>>(gamma, beta);
    k_out   <<<Bn * OCn * OHWn / 4 / 256, 256>>>(out);
}

// round 8
// speedup vs baseline: 1.0936x; 1.0936x over previous
#include <cuda_runtime.h>
#include <math.h>

#define Bn 16
#define Cn 256
#define Hn 128
#define Wn 128
#define HWn (Hn*Wn)
#define PO 20
#define NP (PO*PO)
#define MIDn 16
#define OCn 32
#define OHn 64
#define OWn 64
#define OHWn (OHn*OWn)
#define NBLK_CONV 512

// ---- scratch (static device globals: no allocs allowed) ----
__device__ float g_xp[Bn*Cn*NP];            // pooled 20x20 per (b,c)   [c][n]
__device__ float g_xpT[Bn*NP*Cn];           // transposed pooled        [n][c]
__device__ float g_x2[(size_t)Bn*MIDn*HWn]; // grouped channel means
__device__ float g_attn[Bn*Cn];
__device__ int   g_maxid[MIDn];
__device__ float g_scale[MIDn];
__device__ float g_xc[(size_t)Bn*OCn*HWn];  // concat(x1,x2)
__device__ float g_smean[Bn*HWn];
__device__ float g_smax[Bn*HWn];
__device__ float g_siga[Bn*HWn];            // sigmoid(LSA conv)
__device__ float g_y[(size_t)Bn*OCn*OHWn];  // pre-BN conv output
__device__ float g_part[NBLK_CONV*OCn*2];   // per-block BN partials (fixed slots)
__device__ float g_bnA[OCn];
__device__ float g_bnB[OCn];

__device__ __forceinline__ float fsig(float x) { return 1.0f / (1.0f + __expf(-x)); }

// ---- packed f32x2 helpers ----
__device__ __forceinline__ unsigned long long pk2(float lo, float hi) {
    unsigned long long r;
    asm("mov.b64 %0, {%1, %2};" : "=l"(r) : "f"(lo), "f"(hi));
    return r;
}
__device__ __forceinline__ float2 upk2(unsigned long long u) {
    float2 f;
    asm("mov.b64 {%0, %1}, %2;" : "=f"(f.x), "=f"(f.y) : "l"(u));
    return f;
}
__device__ __forceinline__ void ffma2(unsigned long long& a, unsigned long long v, unsigned long long w) {
    asm("fma.rn.f32x2 %0, %1, %2, %0;" : "+l"(a) : "l"(v), "l"(w));
}
__device__ __forceinline__ unsigned long long fmul2(unsigned long long a, unsigned long long b) {
    unsigned long long r;
    asm("mul.rn.f32x2 %0, %1, %2;" : "=l"(r) : "l"(a), "l"(b));
    return r;
}
__device__ __forceinline__ unsigned long long fadd2(unsigned long long a, unsigned long long b) {
    unsigned long long r;
    asm("add.rn.f32x2 %0, %1, %2;" : "=l"(r) : "l"(a), "l"(b));
    return r;
}

// ---- K1: streaming pool + grouped mean. Block = (b, group, W-half). ----
// Column-bin boundary j=10 lands exactly at col 64, so each half-plane holds
// 10 complete column bins. 512 blocks x 256 thr. One DRAM-cold streaming read
// per half-plane (gm accumulation), row-bin sums re-read L1-hot.
__global__ void __launch_bounds__(256) k_pool_gm(const float* __restrict__ x) {
    int blk = blockIdx.x;                  // b*32 + m*2 + hf
    int b = blk >> 5, m = (blk >> 1) & 15, hf = blk & 1;
    int t = threadIdx.x;
    int hq = hf * 16;                      // quad offset of this half

    __shared__ float4 rb[PO][16];          // row-bin sums for this half
    __shared__ float poolbuf[16][200];     // [c][local n]

    float4 acc[8];
    #pragma unroll
    for (int k = 0; k < 8; k++) acc[k] = make_float4(0.f, 0.f, 0.f, 0.f);

    const float4* base = (const float4*)x + ((size_t)(b * Cn + m * 16)) * 4096;

    for (int c = 0; c < 16; c++) {
        const float4* pl = base + (size_t)c * 4096;
        // streaming read of half-plane (128 rows x 16 quads) + gm accumulation
        #pragma unroll
        for (int k = 0; k < 8; k++) {
            int f = k * 256 + t;           // 0..2047
            int row = f >> 4, q = f & 15;
            float4 v = pl[row * 32 + hq + q];
            acc[k].x += v.x; acc[k].y += v.y; acc[k].z += v.z; acc[k].w += v.w;
        }
        __syncthreads();   // rb free (prior channel consumed)
        // row-bin sums: 20 bins x 16 quads, L1-hot re-read
        for (int it = t; it < PO * 16; it += 256) {
            int i = it >> 4, qc = it & 15;
            int s = (i * Hn) / PO;
            int e = ((i + 1) * Hn + PO - 1) / PO;
            float4 a = make_float4(0.f, 0.f, 0.f, 0.f);
            for (int r = s; r < e; r++) {
                float4 v = pl[r * 32 + hq + qc];
                a.x += v.x; a.y += v.y; a.z += v.z; a.w += v.w;
            }
            rb[i][qc] = a;
        }
        __syncthreads();
        if (t < 200) {
            int i = t / 10, jl = t % 10;
            int j = hf * 10 + jl;
            int si = (i * Hn) / PO, ei = ((i + 1) * Hn + PO - 1) / PO;
            int sj = (j * Wn) / PO - hf * 64;
            int ej = ((j + 1) * Wn + PO - 1) / PO - hf * 64;
            const float* rbf = (const float*)&rb[i][0];   // 64 floats
            float s2 = 0.f;
            for (int w = sj; w < ej; w++) s2 += rbf[w];
            float val = s2 / (float)((ei - si) * (ej - sj));
            g_xp[((size_t)(b * Cn + m * 16 + c)) * NP + i * 20 + j] = val;
            poolbuf[c][t] = val;
        }
    }
    __syncthreads();

    // grouped-mean half-plane write
    float4* x2 = (float4*)g_x2 + ((size_t)(b * MIDn + m)) * 4096;
    #pragma unroll
    for (int k = 0; k < 8; k++) {
        int f = k * 256 + t;
        int row = f >> 4, q = f & 15;
        float4 v = acc[k];
        v.x *= (1.f/16.f); v.y *= (1.f/16.f); v.z *= (1.f/16.f); v.w *= (1.f/16.f);
        x2[row * 32 + hq + q] = v;
    }

    // transposed pooled writes: row n gets this group's 16 channels (64B)
    if (t < 200) {
        int i = t / 10, jl = t % 10;
        int n = i * 20 + hf * 10 + jl;
        float4* dst = (float4*)(g_xpT + ((size_t)b * NP + n) * Cn + m * 16);
        #pragma unroll
        for (int cq = 0; cq < 4; cq++) {
            dst[cq] = make_float4(poolbuf[cq * 4 + 0][t], poolbuf[cq * 4 + 1][t],
                                  poolbuf[cq * 4 + 2][t], poolbuf[cq * 4 + 3][t]);
        }
    }
}

// ---- K2: fused colmean + feat + attn, one block per batch (512 threads) ----
__global__ void __launch_bounds__(512) k_soca(const float* __restrict__ lw,
                                              const float* __restrict__ lb) {
    int b = blockIdx.x;
    int t = threadIdx.x;
    int lane = t & 31, w = t >> 5;       // 16 warps
    __shared__ float cm[NP];
    __shared__ float sf[Cn];
    __shared__ float red[16];

    // stage 1: column means via transposed layout (contiguous per thread)
    float s = 0.f;
    if (t < NP) {
        const float4* row = (const float4*)(g_xpT + ((size_t)b * NP + t) * Cn);
        float4 a0 = make_float4(0.f, 0.f, 0.f, 0.f);
        #pragma unroll 8
        for (int i = 0; i < 64; i++) {
            float4 v = row[i];
            a0.x += v.x; a0.y += v.y; a0.z += v.z; a0.w += v.w;
        }
        s = (a0.x + a0.y + a0.z + a0.w) * (1.0f / Cn);
    }
    float r = (t < NP) ? s : 0.f;
    #pragma unroll
    for (int d = 16; d; d >>= 1) r += __shfl_xor_sync(0xffffffffu, r, d);
    if (lane == 0) red[w] = r;
    __syncthreads();
    float a = 0.f;
    #pragma unroll
    for (int i = 0; i < 16; i++) a += red[i];
    float mm = a * (1.0f / NP);
    if (t < NP) cm[t] = s - mm;
    __syncthreads();

    // stage 2: feat[c] = dot(xp[b,c,:], cm)/(NP-1)
    for (int cc = 0; cc < 16; cc++) {
        int c = w * 16 + cc;
        const float* xp = g_xp + ((size_t)b * Cn + c) * NP;
        float acc = 0.f;
        for (int n = lane; n < NP; n += 32) acc += xp[n] * cm[n];
        #pragma unroll
        for (int d = 16; d; d >>= 1) acc += __shfl_xor_sync(0xffffffffu, acc, d);
        if (lane == 0) sf[c] = acc * (1.0f / (NP - 1));
    }
    __syncthreads();

    // stage 3: attn = sigmoid(feat @ W^T + b)
    for (int oo = 0; oo < 16; oo++) {
        int o = oo * 16 + w;
        const float* wr = lw + o * Cn;
        float acc = 0.f;
        #pragma unroll
        for (int i = lane; i < Cn; i += 32) acc += sf[i] * wr[i];
        #pragma unroll
        for (int d = 16; d; d >>= 1) acc += __shfl_xor_sync(0xffffffffu, acc, d);
        if (lane == 0) g_attn[b * Cn + o] = fsig(acc + lb[o]);
    }
}

// ---- K3: score = mean_b(attn), stable descending top-16, sorted ids ----
__global__ void k_topk() {
    int o = threadIdx.x;   // 256 threads
    __shared__ float sc[Cn];
    __shared__ int fl[Cn];
    float s = 0.f;
    for (int b = 0; b < Bn; b++) s += g_attn[b * Cn + o];
    s *= (1.0f / Bn);
    sc[o] = s;
    __syncthreads();
    float so = sc[o];
    int r = 0;
    for (int j = 0; j < Cn; j++) {
        float sj = sc[j];
        r += (sj > so) || (sj == so && j < o);   // stable argsort(-score)
    }
    fl[o] = (r < MIDn) ? 1 : 0;
    __syncthreads();
    if (r < MIDn) {
        int pos = 0;
        for (int j = 0; j < o; j++) pos += fl[j];
        g_maxid[pos] = o;             // ascending ids == jnp.sort(score_id[:16])
        g_scale[pos] = 1.0f + so;
    }
}

// ---- K4: build xc; two threads per pixel-quad (x1-half / x2-half) ----
__global__ void __launch_bounds__(256) k_build(const float* __restrict__ x) {
    __shared__ int sid[MIDn];
    __shared__ float ssc[MIDn];
    __shared__ float4 s_sum[128];
    __shared__ float4 s_max[128];
    if (threadIdx.x < MIDn) {
        sid[threadIdx.x] = g_maxid[threadIdx.x];
        ssc[threadIdx.x] = g_scale[threadIdx.x];
    }
    __syncthreads();
    int half = threadIdx.x >> 7, lt = threadIdx.x & 127;
    int qg = blockIdx.x * 128 + lt;     // grid = 512 blocks
    int b = qg >> 12;
    int q = qg & 4095;
    float4* xcb = (float4*)g_xc + (size_t)b * OCn * 4096 + q;

    float4 csum = make_float4(0.f, 0.f, 0.f, 0.f);
    float4 cmax = make_float4(-3.4e38f, -3.4e38f, -3.4e38f, -3.4e38f);
    if (half == 0) {
        const float4* xb = (const float4*)x + (size_t)b * Cn * 4096 + q;
        #pragma unroll
        for (int k = 0; k < MIDn; k++) {
            float4 v = xb[(size_t)sid[k] * 4096];
            float sk = ssc[k];
            v.x *= sk; v.y *= sk; v.z *= sk; v.w *= sk;
            xcb[(size_t)k * 4096] = v;
            csum.x += v.x; csum.y += v.y; csum.z += v.z; csum.w += v.w;
            cmax.x = fmaxf(cmax.x, v.x); cmax.y = fmaxf(cmax.y, v.y);
            cmax.z = fmaxf(cmax.z, v.z); cmax.w = fmaxf(cmax.w, v.w);
        }
    } else {
        const float4* x2 = (const float4*)g_x2 + (size_t)b * MIDn * 4096 + q;
        #pragma unroll
        for (int m = 0; m < MIDn; m++) {
            float4 v = x2[(size_t)m * 4096];
            xcb[(size_t)(MIDn + m) * 4096] = v;
            csum.x += v.x; csum.y += v.y; csum.z += v.z; csum.w += v.w;
            cmax.x = fmaxf(cmax.x, v.x); cmax.y = fmaxf(cmax.y, v.y);
            cmax.z = fmaxf(cmax.z, v.z); cmax.w = fmaxf(cmax.w, v.w);
        }
        s_sum[lt] = csum;
        s_max[lt] = cmax;
    }
    __syncthreads();
    if (half == 0) {
        float4 o = s_sum[lt], x4 = s_max[lt];
        csum.x += o.x; csum.y += o.y; csum.z += o.z; csum.w += o.w;
        cmax.x = fmaxf(cmax.x, x4.x); cmax.y = fmaxf(cmax.y, x4.y);
        cmax.z = fmaxf(cmax.z, x4.z); cmax.w = fmaxf(cmax.w, x4.w);
        csum.x *= (1.f/OCn); csum.y *= (1.f/OCn); csum.z *= (1.f/OCn); csum.w *= (1.f/OCn);
        ((float4*)g_smean)[b * 4096 + q] = csum;
        ((float4*)g_smax)[b * 4096 + q] = cmax;
    }
}

// ---- K5: LSA 7x7 conv (2ch -> 1), sigmoid. One block per (b,row) ----
__global__ void k_lsa(const float* __restrict__ lsa) {
    __shared__ float wv[98];
    if (threadIdx.x < 98) wv[threadIdx.x] = lsa[threadIdx.x];
    __syncthreads();
    int b = blockIdx.x >> 7;
    int yr = blockIdx.x & 127;
    int xc = threadIdx.x;   // 128
    const float* pm = g_smean + b * HWn;
    const float* px = g_smax + b * HWn;
    float acc = 0.f;
    #pragma unroll
    for (int dy = 0; dy < 7; dy++) {
        int ry = yr + dy - 3;
        if (ry < 0 || ry >= Hn) continue;
        #pragma unroll
        for (int dx = 0; dx < 7; dx++) {
            int rx = xc + dx - 3;
            if (rx < 0 || rx >= Wn) continue;
            int off = ry * Wn + rx;
            acc += pm[off] * wv[dy * 7 + dx] + px[off] * wv[49 + dy * 7 + dx];
        }
    }
    g_siga[b * HWn + yr * Wn + xc] = fsig(acc);
}

// ---- K6: 3x3/s2 conv with packed f32x2 over output-channel pairs ----
__global__ void __launch_bounds__(128) k_conv(const float* __restrict__ cw,
                                              const float* __restrict__ cb) {
    __shared__ float2 ws2[OCn * 16 * 9];   // [ic][opair][k]
    __shared__ float sb[OCn];
    __shared__ float bred[4][OCn * 2];
    for (int i = threadIdx.x; i < OCn * 16 * 9; i += 128) {
        int ic = i / 144, rr = i % 144, op = rr / 9, k = rr % 9;
        ws2[i] = make_float2(cw[(2 * op) * (OCn * 9) + ic * 9 + k],
                             cw[(2 * op + 1) * (OCn * 9) + ic * 9 + k]);
    }
    if (threadIdx.x < OCn) sb[threadIdx.x] = cb[threadIdx.x];
    __syncthreads();

    int gid = blockIdx.x * 128 + threadIdx.x;  // 65536 output pixels
    int b = gid >> 12;
    int rem = gid & 4095;
    int oy = rem >> 6, ox = rem & 63;
    int iy0 = 2 * oy - 1, ix0 = 2 * ox - 1;

    const float* sg = g_siga + b * HWn;
    float sv[9];
    int offs[9];
    #pragma unroll
    for (int ky = 0; ky < 3; ky++)
        #pragma unroll
        for (int kx = 0; kx < 3; kx++) {
            int iy = iy0 + ky, ix = ix0 + kx;
            bool ok = (iy >= 0 && iy < Hn && ix >= 0 && ix < Wn);
            int iyc = min(max(iy, 0), Hn - 1), ixc = min(max(ix, 0), Wn - 1);
            offs[ky * 3 + kx] = iyc * Wn + ixc;
            sv[ky * 3 + kx] = ok ? sg[iyc * Wn + ixc] : 0.f;
        }

    unsigned long long acc2[16];
    #pragma unroll
    for (int op = 0; op < 16; op++) acc2[op] = pk2(sb[2 * op], sb[2 * op + 1]);

    const float* xcb = g_xc + (size_t)b * OCn * HWn;
    const unsigned long long* wsu = (const unsigned long long*)ws2;
    #pragma unroll 1
    for (int ic = 0; ic < OCn; ic++) {
        const float* pl = xcb + (size_t)ic * HWn;
        unsigned long long v2[9];
        #pragma unroll
        for (int k = 0; k < 9; k++) {
            float v = pl[offs[k]] * sv[k];
            v2[k] = pk2(v, v);
        }
        const unsigned long long* wb = wsu + ic * 144;
        #pragma unroll
        for (int op = 0; op < 16; op++)
            #pragma unroll
            for (int k = 0; k < 9; k++)
                ffma2(acc2[op], v2[k], wb[op * 9 + k]);
    }

    float* yb = g_y + (size_t)b * OCn * OHWn + rem;
    #pragma unroll
    for (int op = 0; op < 16; op++) {
        float2 f = upk2(acc2[op]);
        yb[(size_t)(2 * op) * OHWn] = f.x;
        yb[(size_t)(2 * op + 1) * OHWn] = f.y;
    }

    int lane = threadIdx.x & 31;
    int w = threadIdx.x >> 5;
    #pragma unroll
    for (int op = 0; op < 16; op++) {
        unsigned long long s2 = acc2[op];
        unsigned long long q2 = fmul2(s2, s2);
        #pragma unroll
        for (int d = 16; d; d >>= 1) {
            s2 = fadd2(s2, __shfl_xor_sync(0xffffffffu, s2, d));
            q2 = fadd2(q2, __shfl_xor_sync(0xffffffffu, q2, d));
        }
        if (lane == 0) {
            float2 fs = upk2(s2), fq = upk2(q2);
            bred[w][4 * op + 0] = fs.x;
            bred[w][4 * op + 1] = fq.x;
            bred[w][4 * op + 2] = fs.y;
            bred[w][4 * op + 3] = fq.y;
        }
    }
    __syncthreads();
    if (threadIdx.x < OCn * 2) {
        float t = bred[0][threadIdx.x] + bred[1][threadIdx.x]
                + bred[2][threadIdx.x] + bred[3][threadIdx.x];
        g_part[blockIdx.x * (OCn * 2) + threadIdx.x] = t;
    }
}

// ---- K7: ordered reduction of BN partials -> scale/shift ----
__global__ void k_bnstat(const float* __restrict__ gamma, const float* __restrict__ beta) {
    int t = threadIdx.x;             // 256: stat = t>>2 (64 stats), sub = t&3
    int stat = t >> 2, sub = t & 3;
    float s = 0.f;
    for (int j = 0; j < NBLK_CONV / 4; j++)
        s += g_part[(size_t)(sub + 4 * j) * (OCn * 2) + stat];
    __shared__ float sr[256];
    __shared__ float tot[OCn * 2];
    sr[t] = s;
    __syncthreads();
    if (t < OCn * 2)
        tot[t] = sr[t * 4] + sr[t * 4 + 1] + sr[t * 4 + 2] + sr[t * 4 + 3];
    __syncthreads();
    if (t < OCn) {
        int op = t >> 1, pr = t & 1;
        float sum = tot[4 * op + 2 * pr];
        float sq  = tot[4 * op + 2 * pr + 1];
        float inv = 1.0f / (float)(Bn * OHWn);
        float mu = sum * inv;
        float var = sq * inv - mu * mu;
        int ch = 2 * op + pr;
        float A = gamma[ch] * rsqrtf(var + 1e-3f);
        g_bnA[ch] = A;
        g_bnB[ch] = beta[ch] - mu * A;
    }
}

// ---- K8: BN-normalize + SiLU -> output, float4 ----
__global__ void __launch_bounds__(256) k_out(float* __restrict__ out) {
    int gid = blockIdx.x * 256 + threadIdx.x;       // float4 index
    int ch = (gid >> 10) & 31;                      // 1024 float4 per (b,o) plane
    float A = g_bnA[ch], Bv = g_bnB[ch];
    float4 y = ((const float4*)g_y)[gid];
    float4 r;
    float yn;
    yn = y.x * A + Bv; r.x = yn * fsig(yn);
    yn = y.y * A + Bv; r.y = yn * fsig(yn);
    yn = y.z * A + Bv; r.z = yn * fsig(yn);
    yn = y.w * A + Bv; r.w = yn * fsig(yn);
    ((float4*)out)[gid] = r;
}

extern "C" void kernel_launch(void* const* d_in, const int* in_sizes, int n_in,
                              void* d_out, int out_size) {
    (void)in_sizes; (void)n_in; (void)out_size;
    const float* x     = (const float*)d_in[0];
    const float* lw    = (const float*)d_in[1];
    const float* lb    = (const float*)d_in[2];
    const float* lsa   = (const float*)d_in[3];
    const float* cw    = (const float*)d_in[4];
    const float* cb    = (const float*)d_in[5];
    const float* gamma = (const float*)d_in[6];
    const float* beta  = (const float*)d_in[7];
    float* out = (float*)d_out;

    k_pool_gm<<<Bn * MIDn * 2, 256>>>(x);
    k_soca  <<<Bn, 512>>>(lw, lb);
    k_topk  <<<1, Cn>>>();
    k_build <<<Bn * HWn / 4 / 128, 256>>>(x);
    k_lsa   <<<Bn * Hn, 128>>>(lsa);
    k_conv  <<<NBLK_CONV, 128>>>(cw, cb);
    k_bnstat<<<1, 256>>>(gamma, beta);
    k_out   <<<Bn * OCn * OHWn / 4 / 256, 256>>>(out);
}

// round 10
// speedup vs baseline: 1.2929x; 1.1822x over previous
#include <cuda_runtime.h>
#include <math.h>

#define Bn 16
#define Cn 256
#define Hn 128
#define Wn 128
#define HWn (Hn*Wn)
#define PO 20
#define NP (PO*PO)
#define MIDn 16
#define OCn 32
#define OHn 64
#define OWn 64
#define OHWn (OHn*OWn)
#define NBLK_CONV 512

// ---- scratch (static device globals: no allocs allowed) ----
__device__ float g_xp[Bn*Cn*NP];            // pooled 20x20 per (b,c)   [c][n]
__device__ float g_x2[(size_t)Bn*MIDn*HWn]; // grouped channel means
__device__ float g_attn[Bn*Cn];
__device__ int   g_maxid[MIDn];
__device__ float g_scale[MIDn];
__device__ float g_xc[(size_t)Bn*OCn*HWn];  // concat(x1,x2)
__device__ float g_smean[Bn*HWn];
__device__ float g_smax[Bn*HWn];
__device__ float g_siga[Bn*HWn];            // sigmoid(LSA conv)
__device__ float g_y[(size_t)Bn*OCn*OHWn];  // pre-BN conv output
__device__ float g_part[NBLK_CONV*OCn*2];   // per-block BN partials (fixed slots)
__device__ float g_bnA[OCn];
__device__ float g_bnB[OCn];

__device__ __forceinline__ float fsig(float x) { return 1.0f / (1.0f + __expf(-x)); }

// ---- packed f32x2 helpers ----
__device__ __forceinline__ unsigned long long pk2(float lo, float hi) {
    unsigned long long r;
    asm("mov.b64 %0, {%1, %2};" : "=l"(r) : "f"(lo), "f"(hi));
    return r;
}
__device__ __forceinline__ float2 upk2(unsigned long long u) {
    float2 f;
    asm("mov.b64 {%0, %1}, %2;" : "=f"(f.x), "=f"(f.y) : "l"(u));
    return f;
}
__device__ __forceinline__ void ffma2(unsigned long long& a, unsigned long long v, unsigned long long w) {
    asm("fma.rn.f32x2 %0, %1, %2, %0;" : "+l"(a) : "l"(v), "l"(w));
}
__device__ __forceinline__ unsigned long long fmul2(unsigned long long a, unsigned long long b) {
    unsigned long long r;
    asm("mul.rn.f32x2 %0, %1, %2;" : "=l"(r) : "l"(a), "l"(b));
    return r;
}
__device__ __forceinline__ unsigned long long fadd2(unsigned long long a, unsigned long long b) {
    unsigned long long r;
    asm("add.rn.f32x2 %0, %1, %2;" : "=l"(r) : "l"(a), "l"(b));
    return r;
}

// ---- K1: streaming pool + grouped mean. Block = (b, group, H-half). ----
// Row-bin boundary i=10 lands exactly at row 64, so each 64-row half holds
// 10 complete row bins. 512 blocks x 256 thr; streaming reads are contiguous
// 32KB half-planes; x2 rows are disjoint per half (no combine needed).
__global__ void __launch_bounds__(256) k_pool_gm(const float* __restrict__ x) {
    int blk = blockIdx.x;                  // b*32 + m*2 + hf
    int b = blk >> 5, m = (blk >> 1) & 15, hf = blk & 1;
    int t = threadIdx.x;

    __shared__ float4 rb[10][32];          // 10 local row-bins x 32 col-quads

    float4 acc[8];
    #pragma unroll
    for (int k = 0; k < 8; k++) acc[k] = make_float4(0.f, 0.f, 0.f, 0.f);

    const float4* base = (const float4*)x
        + ((size_t)(b * Cn + m * 16)) * 4096 + hf * 2048;

    for (int c = 0; c < 16; c++) {
        const float4* pl = base + (size_t)c * 4096;
        // contiguous streaming read of half-plane (2048 quads) + gm accumulation
        #pragma unroll
        for (int k = 0; k < 8; k++) {
            float4 v = pl[k * 256 + t];
            acc[k].x += v.x; acc[k].y += v.y; acc[k].z += v.z; acc[k].w += v.w;
        }
        __syncthreads();   // rb from previous channel fully consumed
        // row-bin sums: 10 bins x 32 quads, L1-hot re-read
        for (int it = t; it < 10 * 32; it += 256) {
            int i = it >> 5, qc = it & 31;
            int gi = 10 * hf + i;
            int s = (gi * Hn) / PO - hf * 64;
            int e = ((gi + 1) * Hn + PO - 1) / PO - hf * 64;
            float4 a = make_float4(0.f, 0.f, 0.f, 0.f);
            for (int r = s; r < e; r++) {
                float4 v = pl[r * 32 + qc];
                a.x += v.x; a.y += v.y; a.z += v.z; a.w += v.w;
            }
            rb[i][qc] = a;
        }
        __syncthreads();
        if (t < 200) {
            int i = t / 20, j = t % 20;
            int gi = 10 * hf + i;
            int si = (gi * Hn) / PO, ei = ((gi + 1) * Hn + PO - 1) / PO;
            int sj = (j * Wn) / PO, ej = ((j + 1) * Wn + PO - 1) / PO;
            const float* rbf = (const float*)&rb[i][0];   // 128 floats
            float s2 = 0.f;
            for (int w = sj; w < ej; w++) s2 += rbf[w];
            g_xp[((size_t)(b * Cn + m * 16 + c)) * NP + gi * 20 + j] =
                s2 / (float)((ei - si) * (ej - sj));
        }
    }

    // grouped-mean half-plane write (rows disjoint per half)
    float4* x2 = (float4*)g_x2 + ((size_t)(b * MIDn + m)) * 4096 + hf * 2048;
    #pragma unroll
    for (int k = 0; k < 8; k++) {
        float4 v = acc[k];
        v.x *= (1.f/16.f); v.y *= (1.f/16.f); v.z *= (1.f/16.f); v.w *= (1.f/16.f);
        x2[k * 256 + t] = v;
    }
}

// ---- K2: fused colmean + feat + attn, one block per batch (512 threads) ----
__global__ void __launch_bounds__(512) k_soca(const float* __restrict__ lw,
                                              const float* __restrict__ lb) {
    int b = blockIdx.x;
    int t = threadIdx.x;
    int lane = t & 31, w = t >> 5;       // 16 warps
    __shared__ float cm[NP];
    __shared__ float sf[Cn];
    __shared__ float red[16];

    // stage 1: per-n column mean over channels, then subtract global mean
    float s = 0.f;
    if (t < NP) {
        const float* base = g_xp + (size_t)b * Cn * NP + t;
        #pragma unroll 8
        for (int c = 0; c < Cn; c++) s += base[(size_t)c * NP];
        s *= (1.0f / Cn);
    }
    float r = (t < NP) ? s : 0.f;
    #pragma unroll
    for (int d = 16; d; d >>= 1) r += __shfl_xor_sync(0xffffffffu, r, d);
    if (lane == 0) red[w] = r;
    __syncthreads();
    float a = 0.f;
    #pragma unroll
    for (int i = 0; i < 16; i++) a += red[i];
    float mm = a * (1.0f / NP);
    if (t < NP) cm[t] = s - mm;
    __syncthreads();

    // stage 2: feat[c] = dot(xp[b,c,:], cm)/(NP-1)
    for (int cc = 0; cc < 16; cc++) {
        int c = w * 16 + cc;
        const float* xp = g_xp + ((size_t)b * Cn + c) * NP;
        float acc = 0.f;
        for (int n = lane; n < NP; n += 32) acc += xp[n] * cm[n];
        #pragma unroll
        for (int d = 16; d; d >>= 1) acc += __shfl_xor_sync(0xffffffffu, acc, d);
        if (lane == 0) sf[c] = acc * (1.0f / (NP - 1));
    }
    __syncthreads();

    // stage 3: attn = sigmoid(feat @ W^T + b)
    for (int oo = 0; oo < 16; oo++) {
        int o = oo * 16 + w;
        const float* wr = lw + o * Cn;
        float acc = 0.f;
        #pragma unroll
        for (int i = lane; i < Cn; i += 32) acc += sf[i] * wr[i];
        #pragma unroll
        for (int d = 16; d; d >>= 1) acc += __shfl_xor_sync(0xffffffffu, acc, d);
        if (lane == 0) g_attn[b * Cn + o] = fsig(acc + lb[o]);
    }
}

// ---- K3: score = mean_b(attn), stable descending top-16, sorted ids ----
__global__ void k_topk() {
    int o = threadIdx.x;   // 256 threads
    __shared__ float sc[Cn];
    __shared__ int fl[Cn];
    float s = 0.f;
    for (int b = 0; b < Bn; b++) s += g_attn[b * Cn + o];
    s *= (1.0f / Bn);
    sc[o] = s;
    __syncthreads();
    float so = sc[o];
    int r = 0;
    for (int j = 0; j < Cn; j++) {
        float sj = sc[j];
        r += (sj > so) || (sj == so && j < o);   // stable argsort(-score)
    }
    fl[o] = (r < MIDn) ? 1 : 0;
    __syncthreads();
    if (r < MIDn) {
        int pos = 0;
        for (int j = 0; j < o; j++) pos += fl[j];
        g_maxid[pos] = o;             // ascending ids == jnp.sort(score_id[:16])
        g_scale[pos] = 1.0f + so;
    }
}

// ---- K4: build xc; two threads per pixel-quad (x1-half / x2-half) ----
__global__ void __launch_bounds__(256) k_build(const float* __restrict__ x) {
    __shared__ int sid[MIDn];
    __shared__ float ssc[MIDn];
    __shared__ float4 s_sum[128];
    __shared__ float4 s_max[128];
    if (threadIdx.x < MIDn) {
        sid[threadIdx.x] = g_maxid[threadIdx.x];
        ssc[threadIdx.x] = g_scale[threadIdx.x];
    }
    __syncthreads();
    int half = threadIdx.x >> 7, lt = threadIdx.x & 127;
    int qg = blockIdx.x * 128 + lt;     // grid = 512 blocks
    int b = qg >> 12;
    int q = qg & 4095;
    float4* xcb = (float4*)g_xc + (size_t)b * OCn * 4096 + q;

    float4 csum = make_float4(0.f, 0.f, 0.f, 0.f);
    float4 cmax = make_float4(-3.4e38f, -3.4e38f, -3.4e38f, -3.4e38f);
    if (half == 0) {
        const float4* xb = (const float4*)x + (size_t)b * Cn * 4096 + q;
        #pragma unroll
        for (int k = 0; k < MIDn; k++) {
            float4 v = xb[(size_t)sid[k] * 4096];
            float sk = ssc[k];
            v.x *= sk; v.y *= sk; v.z *= sk; v.w *= sk;
            xcb[(size_t)k * 4096] = v;
            csum.x += v.x; csum.y += v.y; csum.z += v.z; csum.w += v.w;
            cmax.x = fmaxf(cmax.x, v.x); cmax.y = fmaxf(cmax.y, v.y);
            cmax.z = fmaxf(cmax.z, v.z); cmax.w = fmaxf(cmax.w, v.w);
        }
    } else {
        const float4* x2 = (const float4*)g_x2 + (size_t)b * MIDn * 4096 + q;
        #pragma unroll
        for (int m = 0; m < MIDn; m++) {
            float4 v = x2[(size_t)m * 4096];
            xcb[(size_t)(MIDn + m) * 4096] = v;
            csum.x += v.x; csum.y += v.y; csum.z += v.z; csum.w += v.w;
            cmax.x = fmaxf(cmax.x, v.x); cmax.y = fmaxf(cmax.y, v.y);
            cmax.z = fmaxf(cmax.z, v.z); cmax.w = fmaxf(cmax.w, v.w);
        }
        s_sum[lt] = csum;
        s_max[lt] = cmax;
    }
    __syncthreads();
    if (half == 0) {
        float4 o = s_sum[lt], x4 = s_max[lt];
        csum.x += o.x; csum.y += o.y; csum.z += o.z; csum.w += o.w;
        cmax.x = fmaxf(cmax.x, x4.x); cmax.y = fmaxf(cmax.y, x4.y);
        cmax.z = fmaxf(cmax.z, x4.z); cmax.w = fmaxf(cmax.w, x4.w);
        csum.x *= (1.f/OCn); csum.y *= (1.f/OCn); csum.z *= (1.f/OCn); csum.w *= (1.f/OCn);
        ((float4*)g_smean)[b * 4096 + q] = csum;
        ((float4*)g_smax)[b * 4096 + q] = cmax;
    }
}

// ---- K5: LSA 7x7 conv (2ch -> 1), sigmoid. One block per (b,row) ----
__global__ void k_lsa(const float* __restrict__ lsa) {
    __shared__ float wv[98];
    if (threadIdx.x < 98) wv[threadIdx.x] = lsa[threadIdx.x];
    __syncthreads();
    int b = blockIdx.x >> 7;
    int yr = blockIdx.x & 127;
    int xc = threadIdx.x;   // 128
    const float* pm = g_smean + b * HWn;
    const float* px = g_smax + b * HWn;
    float acc = 0.f;
    #pragma unroll
    for (int dy = 0; dy < 7; dy++) {
        int ry = yr + dy - 3;
        if (ry < 0 || ry >= Hn) continue;
        #pragma unroll
        for (int dx = 0; dx < 7; dx++) {
            int rx = xc + dx - 3;
            if (rx < 0 || rx >= Wn) continue;
            int off = ry * Wn + rx;
            acc += pm[off] * wv[dy * 7 + dx] + px[off] * wv[49 + dy * 7 + dx];
        }
    }
    g_siga[b * HWn + yr * Wn + xc] = fsig(acc);
}

// ---- K6: 3x3/s2 conv with packed f32x2 over output-channel pairs ----
__global__ void __launch_bounds__(128) k_conv(const float* __restrict__ cw,
                                              const float* __restrict__ cb) {
    __shared__ float2 ws2[OCn * 16 * 9];   // [ic][opair][k]
    __shared__ float sb[OCn];
    __shared__ float bred[4][OCn * 2];
    for (int i = threadIdx.x; i < OCn * 16 * 9; i += 128) {
        int ic = i / 144, rr = i % 144, op = rr / 9, k = rr % 9;
        ws2[i] = make_float2(cw[(2 * op) * (OCn * 9) + ic * 9 + k],
                             cw[(2 * op + 1) * (OCn * 9) + ic * 9 + k]);
    }
    if (threadIdx.x < OCn) sb[threadIdx.x] = cb[threadIdx.x];
    __syncthreads();

    int gid = blockIdx.x * 128 + threadIdx.x;  // 65536 output pixels
    int b = gid >> 12;
    int rem = gid & 4095;
    int oy = rem >> 6, ox = rem & 63;
    int iy0 = 2 * oy - 1, ix0 = 2 * ox - 1;

    const float* sg = g_siga + b * HWn;
    float sv[9];
    int offs[9];
    #pragma unroll
    for (int ky = 0; ky < 3; ky++)
        #pragma unroll
        for (int kx = 0; kx < 3; kx++) {
            int iy = iy0 + ky, ix = ix0 + kx;
            bool ok = (iy >= 0 && iy < Hn && ix >= 0 && ix < Wn);
            int iyc = min(max(iy, 0), Hn - 1), ixc = min(max(ix, 0), Wn - 1);
            offs[ky * 3 + kx] = iyc * Wn + ixc;
            sv[ky * 3 + kx] = ok ? sg[iyc * Wn + ixc] : 0.f;
        }

    unsigned long long acc2[16];
    #pragma unroll
    for (int op = 0; op < 16; op++) acc2[op] = pk2(sb[2 * op], sb[2 * op + 1]);

    const float* xcb = g_xc + (size_t)b * OCn * HWn;
    const unsigned long long* wsu = (const unsigned long long*)ws2;
    #pragma unroll 1
    for (int ic = 0; ic < OCn; ic++) {
        const float* pl = xcb + (size_t)ic * HWn;
        unsigned long long v2[9];
        #pragma unroll
        for (int k = 0; k < 9; k++) {
            float v = pl[offs[k]] * sv[k];
            v2[k] = pk2(v, v);
        }
        const unsigned long long* wb = wsu + ic * 144;
        #pragma unroll
        for (int op = 0; op < 16; op++)
            #pragma unroll
            for (int k = 0; k < 9; k++)
                ffma2(acc2[op], v2[k], wb[op * 9 + k]);
    }

    float* yb = g_y + (size_t)b * OCn * OHWn + rem;
    #pragma unroll
    for (int op = 0; op < 16; op++) {
        float2 f = upk2(acc2[op]);
        yb[(size_t)(2 * op) * OHWn] = f.x;
        yb[(size_t)(2 * op + 1) * OHWn] = f.y;
    }

    int lane = threadIdx.x & 31;
    int w = threadIdx.x >> 5;
    #pragma unroll
    for (int op = 0; op < 16; op++) {
        unsigned long long s2 = acc2[op];
        unsigned long long q2 = fmul2(s2, s2);
        #pragma unroll
        for (int d = 16; d; d >>= 1) {
            s2 = fadd2(s2, __shfl_xor_sync(0xffffffffu, s2, d));
            q2 = fadd2(q2, __shfl_xor_sync(0xffffffffu, q2, d));
        }
        if (lane == 0) {
            float2 fs = upk2(s2), fq = upk2(q2);
            bred[w][4 * op + 0] = fs.x;
            bred[w][4 * op + 1] = fq.x;
            bred[w][4 * op + 2] = fs.y;
            bred[w][4 * op + 3] = fq.y;
        }
    }
    __syncthreads();
    if (threadIdx.x < OCn * 2) {
        float t = bred[0][threadIdx.x] + bred[1][threadIdx.x]
                + bred[2][threadIdx.x] + bred[3][threadIdx.x];
        g_part[blockIdx.x * (OCn * 2) + threadIdx.x] = t;
    }
}

// ---- K7: ordered reduction of BN partials -> scale/shift ----
__global__ void k_bnstat(const float* __restrict__ gamma, const float* __restrict__ beta) {
    int t = threadIdx.x;             // 256: stat = t>>2 (64 stats), sub = t&3
    int stat = t >> 2, sub = t & 3;
    float s = 0.f;
    for (int j = 0; j < NBLK_CONV / 4; j++)
        s += g_part[(size_t)(sub + 4 * j) * (OCn * 2) + stat];
    __shared__ float sr[256];
    __shared__ float tot[OCn * 2];
    sr[t] = s;
    __syncthreads();
    if (t < OCn * 2)
        tot[t] = sr[t * 4] + sr[t * 4 + 1] + sr[t * 4 + 2] + sr[t * 4 + 3];
    __syncthreads();
    if (t < OCn) {
        int op = t >> 1, pr = t & 1;
        float sum = tot[4 * op + 2 * pr];
        float sq  = tot[4 * op + 2 * pr + 1];
        float inv = 1.0f / (float)(Bn * OHWn);
        float mu = sum * inv;
        float var = sq * inv - mu * mu;
        int ch = 2 * op + pr;
        float A = gamma[ch] * rsqrtf(var + 1e-3f);
        g_bnA[ch] = A;
        g_bnB[ch] = beta[ch] - mu * A;
    }
}

// ---- K8: BN-normalize + SiLU -> output, float4 ----
__global__ void __launch_bounds__(256) k_out(float* __restrict__ out) {
    int gid = blockIdx.x * 256 + threadIdx.x;       // float4 index
    int ch = (gid >> 10) & 31;                      // 1024 float4 per (b,o) plane
    float A = g_bnA[ch], Bv = g_bnB[ch];
    float4 y = ((const float4*)g_y)[gid];
    float4 r;
    float yn;
    yn = y.x * A + Bv; r.x = yn * fsig(yn);
    yn = y.y * A + Bv; r.y = yn * fsig(yn);
    yn = y.z * A + Bv; r.z = yn * fsig(yn);
    yn = y.w * A + Bv; r.w = yn * fsig(yn);
    ((float4*)out)[gid] = r;
}

extern "C" void kernel_launch(void* const* d_in, const int* in_sizes, int n_in,
                              void* d_out, int out_size) {
    (void)in_sizes; (void)n_in; (void)out_size;
    const float* x     = (const float*)d_in[0];
    const float* lw    = (const float*)d_in[1];
    const float* lb    = (const float*)d_in[2];
    const float* lsa   = (const float*)d_in[3];
    const float* cw    = (const float*)d_in[4];
    const float* cb    = (const float*)d_in[5];
    const float* gamma = (const float*)d_in[6];
    const float* beta  = (const float*)d_in[7];
    float* out = (float*)d_out;

    k_pool_gm<<<Bn * MIDn * 2, 256>>>(x);
    k_soca  <<<Bn, 512>>>(lw, lb);
    k_topk  <<<1, Cn>>>();
    k_build <<<Bn * HWn / 4 / 128, 256>>>(x);
    k_lsa   <<<Bn * Hn, 128>>>(lsa);
    k_conv  <<<NBLK_CONV, 128>>>(cw, cb);
    k_bnstat<<<1, 256>>>(gamma, beta);
    k_out   <<<Bn * OCn * OHWn / 4 / 256, 256>>>(out);
}

// round 12
// speedup vs baseline: 1.4541x; 1.1247x over previous
#include <cuda_runtime.h>
#include <math.h>

#define Bn 16
#define Cn 256
#define Hn 128
#define Wn 128
#define HWn (Hn*Wn)
#define PO 20
#define NP (PO*PO)
#define MIDn 16
#define OCn 32
#define OHn 64
#define OWn 64
#define OHWn (OHn*OWn)
#define NBLK_CONV 512

// ---- scratch (static device globals: no allocs allowed) ----
__device__ float g_xp[Bn*Cn*NP];            // pooled 20x20 per (b,c)   [c][n]
__device__ float g_x2[(size_t)Bn*MIDn*HWn]; // grouped channel means
__device__ float g_attn[Bn*Cn];
__device__ int   g_maxid[MIDn];
__device__ float g_scale[MIDn];
__device__ float g_xc[(size_t)Bn*OCn*HWn];  // concat(x1,x2)
__device__ float g_smean[Bn*HWn];
__device__ float g_smax[Bn*HWn];
__device__ float g_siga[Bn*HWn];            // sigmoid(LSA conv)
__device__ float g_y[(size_t)Bn*OCn*OHWn];  // pre-BN conv output
__device__ float g_part[NBLK_CONV*OCn*2];   // per-block BN partials (fixed slots)
__device__ float g_bnA[OCn];
__device__ float g_bnB[OCn];

__device__ __forceinline__ float fsig(float x) { return 1.0f / (1.0f + __expf(-x)); }

// ---- packed f32x2 helpers ----
__device__ __forceinline__ unsigned long long pk2(float lo, float hi) {
    unsigned long long r;
    asm("mov.b64 %0, {%1, %2};" : "=l"(r) : "f"(lo), "f"(hi));
    return r;
}
__device__ __forceinline__ float2 upk2(unsigned long long u) {
    float2 f;
    asm("mov.b64 {%0, %1}, %2;" : "=f"(f.x), "=f"(f.y) : "l"(u));
    return f;
}
__device__ __forceinline__ void ffma2(unsigned long long& a, unsigned long long v, unsigned long long w) {
    asm("fma.rn.f32x2 %0, %1, %2, %0;" : "+l"(a) : "l"(v), "l"(w));
}
__device__ __forceinline__ unsigned long long fmul2(unsigned long long a, unsigned long long b) {
    unsigned long long r;
    asm("mul.rn.f32x2 %0, %1, %2;" : "=l"(r) : "l"(a), "l"(b));
    return r;
}
__device__ __forceinline__ unsigned long long fadd2(unsigned long long a, unsigned long long b) {
    unsigned long long r;
    asm("add.rn.f32x2 %0, %1, %2;" : "=l"(r) : "l"(a), "l"(b));
    return r;
}

// ---- K1: fused adaptive-pool + grouped channel mean (R4 structure). ----
// One block per (b, group): streams 16 full planes contiguously (8 float4 per
// thread per channel), accumulates group mean in registers, computes the 20x20
// pool via L1-hot re-reads. rb is double-buffered: 1 barrier per channel.
__global__ void __launch_bounds__(512) k_pool_gm(const float* __restrict__ x) {
    int b = blockIdx.x >> 4, m = blockIdx.x & 15;
    int t = threadIdx.x;
    __shared__ float4 rb[2][PO][32];   // double-buffered row-bin sums

    float4 acc[8];
    #pragma unroll
    for (int j = 0; j < 8; j++) acc[j] = make_float4(0.f, 0.f, 0.f, 0.f);

    const float4* base = (const float4*)x + ((size_t)(b * Cn + m * 16)) * 4096;

    for (int c = 0; c < 16; c++) {
        const float4* pl = base + (size_t)c * 4096;
        int buf = c & 1;
        // streaming read (contiguous, 8 independent float4 per thread)
        #pragma unroll
        for (int j = 0; j < 8; j++) {
            float4 v = pl[j * 512 + t];
            acc[j].x += v.x; acc[j].y += v.y; acc[j].z += v.z; acc[j].w += v.w;
        }
        // row-bin sums: 640 items (bin i, col-quad qc); plane is L1-hot.
        // Writes go to rb[buf]; readers of rb[buf^1] (prev channel) were
        // ordered by the previous iteration's barrier.
        for (int it = t; it < PO * 32; it += 512) {
            int i = it >> 5, qc = it & 31;
            int s = (i * Hn) / PO;
            int e = ((i + 1) * Hn + PO - 1) / PO;
            float4 a = make_float4(0.f, 0.f, 0.f, 0.f);
            for (int r = s; r < e; r++) {
                float4 v = pl[r * 32 + qc];
                a.x += v.x; a.y += v.y; a.z += v.z; a.w += v.w;
            }
            rb[buf][i][qc] = a;
        }
        __syncthreads();
        if (t < NP) {
            int i = t / PO, j = t % PO;
            int si = (i * Hn) / PO, ei = ((i + 1) * Hn + PO - 1) / PO;
            int sj = (j * Wn) / PO, ej = ((j + 1) * Wn + PO - 1) / PO;
            const float* rbf = (const float*)&rb[buf][i][0];
            float s2 = 0.f;
            for (int w = sj; w < ej; w++) s2 += rbf[w];
            g_xp[((size_t)(b * Cn + m * 16 + c)) * NP + t] =
                s2 / (float)((ei - si) * (ej - sj));
        }
    }

    float4* x2 = (float4*)g_x2 + ((size_t)(b * MIDn + m)) * 4096;
    #pragma unroll
    for (int j = 0; j < 8; j++) {
        float4 v = acc[j];
        v.x *= (1.f/16.f); v.y *= (1.f/16.f); v.z *= (1.f/16.f); v.w *= (1.f/16.f);
        x2[j * 512 + t] = v;
    }
}

// ---- K2: fused colmean + feat + attn, one block per batch (512 threads) ----
__global__ void __launch_bounds__(512) k_soca(const float* __restrict__ lw,
                                              const float* __restrict__ lb) {
    int b = blockIdx.x;
    int t = threadIdx.x;
    int lane = t & 31, w = t >> 5;       // 16 warps
    __shared__ float cm[NP];
    __shared__ float sf[Cn];
    __shared__ float red[16];

    // stage 1: per-n column mean over channels (coalesced across t)
    float s = 0.f;
    if (t < NP) {
        const float* base = g_xp + (size_t)b * Cn * NP + t;
        #pragma unroll 8
        for (int c = 0; c < Cn; c++) s += base[(size_t)c * NP];
        s *= (1.0f / Cn);
    }
    float r = (t < NP) ? s : 0.f;
    #pragma unroll
    for (int d = 16; d; d >>= 1) r += __shfl_xor_sync(0xffffffffu, r, d);
    if (lane == 0) red[w] = r;
    __syncthreads();
    float a = 0.f;
    #pragma unroll
    for (int i = 0; i < 16; i++) a += red[i];
    float mm = a * (1.0f / NP);
    if (t < NP) cm[t] = s - mm;
    __syncthreads();

    // stage 2: feat[c] = dot(xp[b,c,:], cm)/(NP-1)
    for (int cc = 0; cc < 16; cc++) {
        int c = w * 16 + cc;
        const float* xp = g_xp + ((size_t)b * Cn + c) * NP;
        float acc = 0.f;
        for (int n = lane; n < NP; n += 32) acc += xp[n] * cm[n];
        #pragma unroll
        for (int d = 16; d; d >>= 1) acc += __shfl_xor_sync(0xffffffffu, acc, d);
        if (lane == 0) sf[c] = acc * (1.0f / (NP - 1));
    }
    __syncthreads();

    // stage 3: attn = sigmoid(feat @ W^T + b)
    for (int oo = 0; oo < 16; oo++) {
        int o = oo * 16 + w;
        const float* wr = lw + o * Cn;
        float acc = 0.f;
        #pragma unroll
        for (int i = lane; i < Cn; i += 32) acc += sf[i] * wr[i];
        #pragma unroll
        for (int d = 16; d; d >>= 1) acc += __shfl_xor_sync(0xffffffffu, acc, d);
        if (lane == 0) g_attn[b * Cn + o] = fsig(acc + lb[o]);
    }
}

// ---- K3: score = mean_b(attn), stable descending top-16, sorted ids ----
__global__ void k_topk() {
    int o = threadIdx.x;   // 256 threads
    __shared__ float sc[Cn];
    __shared__ int fl[Cn];
    float s = 0.f;
    for (int b = 0; b < Bn; b++) s += g_attn[b * Cn + o];
    s *= (1.0f / Bn);
    sc[o] = s;
    __syncthreads();
    float so = sc[o];
    int r = 0;
    for (int j = 0; j < Cn; j++) {
        float sj = sc[j];
        r += (sj > so) || (sj == so && j < o);   // stable argsort(-score)
    }
    fl[o] = (r < MIDn) ? 1 : 0;
    __syncthreads();
    if (r < MIDn) {
        int pos = 0;
        for (int j = 0; j < o; j++) pos += fl[j];
        g_maxid[pos] = o;             // ascending ids == jnp.sort(score_id[:16])
        g_scale[pos] = 1.0f + so;
    }
}

// ---- K4: build xc; two threads per pixel-quad (x1-half / x2-half) ----
__global__ void __launch_bounds__(256) k_build(const float* __restrict__ x) {
    __shared__ int sid[MIDn];
    __shared__ float ssc[MIDn];
    __shared__ float4 s_sum[128];
    __shared__ float4 s_max[128];
    if (threadIdx.x < MIDn) {
        sid[threadIdx.x] = g_maxid[threadIdx.x];
        ssc[threadIdx.x] = g_scale[threadIdx.x];
    }
    __syncthreads();
    int half = threadIdx.x >> 7, lt = threadIdx.x & 127;
    int qg = blockIdx.x * 128 + lt;     // grid = 512 blocks
    int b = qg >> 12;
    int q = qg & 4095;
    float4* xcb = (float4*)g_xc + (size_t)b * OCn * 4096 + q;

    float4 csum = make_float4(0.f, 0.f, 0.f, 0.f);
    float4 cmax = make_float4(-3.4e38f, -3.4e38f, -3.4e38f, -3.4e38f);
    if (half == 0) {
        const float4* xb = (const float4*)x + (size_t)b * Cn * 4096 + q;
        #pragma unroll
        for (int k = 0; k < MIDn; k++) {
            float4 v = xb[(size_t)sid[k] * 4096];
            float sk = ssc[k];
            v.x *= sk; v.y *= sk; v.z *= sk; v.w *= sk;
            xcb[(size_t)k * 4096] = v;
            csum.x += v.x; csum.y += v.y; csum.z += v.z; csum.w += v.w;
            cmax.x = fmaxf(cmax.x, v.x); cmax.y = fmaxf(cmax.y, v.y);
            cmax.z = fmaxf(cmax.z, v.z); cmax.w = fmaxf(cmax.w, v.w);
        }
    } else {
        const float4* x2 = (const float4*)g_x2 + (size_t)b * MIDn * 4096 + q;
        #pragma unroll
        for (int m = 0; m < MIDn; m++) {
            float4 v = x2[(size_t)m * 4096];
            xcb[(size_t)(MIDn + m) * 4096] = v;
            csum.x += v.x; csum.y += v.y; csum.z += v.z; csum.w += v.w;
            cmax.x = fmaxf(cmax.x, v.x); cmax.y = fmaxf(cmax.y, v.y);
            cmax.z = fmaxf(cmax.z, v.z); cmax.w = fmaxf(cmax.w, v.w);
        }
        s_sum[lt] = csum;
        s_max[lt] = cmax;
    }
    __syncthreads();
    if (half == 0) {
        float4 o = s_sum[lt], x4 = s_max[lt];
        csum.x += o.x; csum.y += o.y; csum.z += o.z; csum.w += o.w;
        cmax.x = fmaxf(cmax.x, x4.x); cmax.y = fmaxf(cmax.y, x4.y);
        cmax.z = fmaxf(cmax.z, x4.z); cmax.w = fmaxf(cmax.w, x4.w);
        csum.x *= (1.f/OCn); csum.y *= (1.f/OCn); csum.z *= (1.f/OCn); csum.w *= (1.f/OCn);
        ((float4*)g_smean)[b * 4096 + q] = csum;
        ((float4*)g_smax)[b * 4096 + q] = cmax;
    }
}

// ---- K5: LSA 7x7 conv (2ch -> 1), sigmoid. One block per (b,row) ----
__global__ void k_lsa(const float* __restrict__ lsa) {
    __shared__ float wv[98];
    if (threadIdx.x < 98) wv[threadIdx.x] = lsa[threadIdx.x];
    __syncthreads();
    int b = blockIdx.x >> 7;
    int yr = blockIdx.x & 127;
    int xc = threadIdx.x;   // 128
    const float* pm = g_smean + b * HWn;
    const float* px = g_smax + b * HWn;
    float acc = 0.f;
    #pragma unroll
    for (int dy = 0; dy < 7; dy++) {
        int ry = yr + dy - 3;
        if (ry < 0 || ry >= Hn) continue;
        #pragma unroll
        for (int dx = 0; dx < 7; dx++) {
            int rx = xc + dx - 3;
            if (rx < 0 || rx >= Wn) continue;
            int off = ry * Wn + rx;
            acc += pm[off] * wv[dy * 7 + dx] + px[off] * wv[49 + dy * 7 + dx];
        }
    }
    g_siga[b * HWn + yr * Wn + xc] = fsig(acc);
}

// ---- K6: 3x3/s2 conv with packed f32x2 over output-channel pairs ----
__global__ void __launch_bounds__(128) k_conv(const float* __restrict__ cw,
                                              const float* __restrict__ cb) {
    __shared__ float2 ws2[OCn * 16 * 9];   // [ic][opair][k]
    __shared__ float sb[OCn];
    __shared__ float bred[4][OCn * 2];
    for (int i = threadIdx.x; i < OCn * 16 * 9; i += 128) {
        int ic = i / 144, rr = i % 144, op = rr / 9, k = rr % 9;
        ws2[i] = make_float2(cw[(2 * op) * (OCn * 9) + ic * 9 + k],
                             cw[(2 * op + 1) * (OCn * 9) + ic * 9 + k]);
    }
    if (threadIdx.x < OCn) sb[threadIdx.x] = cb[threadIdx.x];
    __syncthreads();

    int gid = blockIdx.x * 128 + threadIdx.x;  // 65536 output pixels
    int b = gid >> 12;
    int rem = gid & 4095;
    int oy = rem >> 6, ox = rem & 63;
    int iy0 = 2 * oy - 1, ix0 = 2 * ox - 1;

    const float* sg = g_siga + b * HWn;
    float sv[9];
    int offs[9];
    #pragma unroll
    for (int ky = 0; ky < 3; ky++)
        #pragma unroll
        for (int kx = 0; kx < 3; kx++) {
            int iy = iy0 + ky, ix = ix0 + kx;
            bool ok = (iy >= 0 && iy < Hn && ix >= 0 && ix < Wn);
            int iyc = min(max(iy, 0), Hn - 1), ixc = min(max(ix, 0), Wn - 1);
            offs[ky * 3 + kx] = iyc * Wn + ixc;
            sv[ky * 3 + kx] = ok ? sg[iyc * Wn + ixc] : 0.f;
        }

    unsigned long long acc2[16];
    #pragma unroll
    for (int op = 0; op < 16; op++) acc2[op] = pk2(sb[2 * op], sb[2 * op + 1]);

    const float* xcb = g_xc + (size_t)b * OCn * HWn;
    const unsigned long long* wsu = (const unsigned long long*)ws2;
    #pragma unroll 1
    for (int ic = 0; ic < OCn; ic++) {
        const float* pl = xcb + (size_t)ic * HWn;
        unsigned long long v2[9];
        #pragma unroll
        for (int k = 0; k < 9; k++) {
            float v = pl[offs[k]] * sv[k];
            v2[k] = pk2(v, v);
        }
        const unsigned long long* wb = wsu + ic * 144;
        #pragma unroll
        for (int op = 0; op < 16; op++)
            #pragma unroll
            for (int k = 0; k < 9; k++)
                ffma2(acc2[op], v2[k], wb[op * 9 + k]);
    }

    float* yb = g_y + (size_t)b * OCn * OHWn + rem;
    #pragma unroll
    for (int op = 0; op < 16; op++) {
        float2 f = upk2(acc2[op]);
        yb[(size_t)(2 * op) * OHWn] = f.x;
        yb[(size_t)(2 * op + 1) * OHWn] = f.y;
    }

    int lane = threadIdx.x & 31;
    int w = threadIdx.x >> 5;
    #pragma unroll
    for (int op = 0; op < 16; op++) {
        unsigned long long s2 = acc2[op];
        unsigned long long q2 = fmul2(s2, s2);
        #pragma unroll
        for (int d = 16; d; d >>= 1) {
            s2 = fadd2(s2, __shfl_xor_sync(0xffffffffu, s2, d));
            q2 = fadd2(q2, __shfl_xor_sync(0xffffffffu, q2, d));
        }
        if (lane == 0) {
            float2 fs = upk2(s2), fq = upk2(q2);
            bred[w][4 * op + 0] = fs.x;
            bred[w][4 * op + 1] = fq.x;
            bred[w][4 * op + 2] = fs.y;
            bred[w][4 * op + 3] = fq.y;
        }
    }
    __syncthreads();
    if (threadIdx.x < OCn * 2) {
        float t = bred[0][threadIdx.x] + bred[1][threadIdx.x]
                + bred[2][threadIdx.x] + bred[3][threadIdx.x];
        g_part[blockIdx.x * (OCn * 2) + threadIdx.x] = t;
    }
}

// ---- K7: ordered reduction of BN partials -> scale/shift ----
__global__ void k_bnstat(const float* __restrict__ gamma, const float* __restrict__ beta) {
    int t = threadIdx.x;             // 256: stat = t>>2 (64 stats), sub = t&3
    int stat = t >> 2, sub = t & 3;
    float s = 0.f;
    for (int j = 0; j < NBLK_CONV / 4; j++)
        s += g_part[(size_t)(sub + 4 * j) * (OCn * 2) + stat];
    __shared__ float sr[256];
    __shared__ float tot[OCn * 2];
    sr[t] = s;
    __syncthreads();
    if (t < OCn * 2)
        tot[t] = sr[t * 4] + sr[t * 4 + 1] + sr[t * 4 + 2] + sr[t * 4 + 3];
    __syncthreads();
    if (t < OCn) {
        int op = t >> 1, pr = t & 1;
        float sum = tot[4 * op + 2 * pr];
        float sq  = tot[4 * op + 2 * pr + 1];
        float inv = 1.0f / (float)(Bn * OHWn);
        float mu = sum * inv;
        float var = sq * inv - mu * mu;
        int ch = 2 * op + pr;
        float A = gamma[ch] * rsqrtf(var + 1e-3f);
        g_bnA[ch] = A;
        g_bnB[ch] = beta[ch] - mu * A;
    }
}

// ---- K8: BN-normalize + SiLU -> output, float4 ----
__global__ void __launch_bounds__(256) k_out(float* __restrict__ out) {
    int gid = blockIdx.x * 256 + threadIdx.x;       // float4 index
    int ch = (gid >> 10) & 31;                      // 1024 float4 per (b,o) plane
    float A = g_bnA[ch], Bv = g_bnB[ch];
    float4 y = ((const float4*)g_y)[gid];
    float4 r;
    float yn;
    yn = y.x * A + Bv; r.x = yn * fsig(yn);
    yn = y.y * A + Bv; r.y = yn * fsig(yn);
    yn = y.z * A + Bv; r.z = yn * fsig(yn);
    yn = y.w * A + Bv; r.w = yn * fsig(yn);
    ((float4*)out)[gid] = r;
}

extern "C" void kernel_launch(void* const* d_in, const int* in_sizes, int n_in,
                              void* d_out, int out_size) {
    (void)in_sizes; (void)n_in; (void)out_size;
    const float* x     = (const float*)d_in[0];
    const float* lw    = (const float*)d_in[1];
    const float* lb    = (const float*)d_in[2];
    const float* lsa   = (const float*)d_in[3];
    const float* cw    = (const float*)d_in[4];
    const float* cb    = (const float*)d_in[5];
    const float* gamma = (const float*)d_in[6];
    const float* beta  = (const float*)d_in[7];
    float* out = (float*)d_out;

    k_pool_gm<<<Bn * MIDn, 512>>>(x);
    k_soca  <<<Bn, 512>>>(lw, lb);
    k_topk  <<<1, Cn>>>();
    k_build <<<Bn * HWn / 4 / 128, 256>>>(x);
    k_lsa   <<<Bn * Hn, 128>>>(lsa);
    k_conv  <<<NBLK_CONV, 128>>>(cw, cb);
    k_bnstat<<<1, 256>>>(gamma, beta);
    k_out   <<<Bn * OCn * OHWn / 4 / 256, 256>>>(out);
}